// round 7
// baseline (speedup 1.0000x reference)
#include <cuda_runtime.h>
#include <math.h>
#include <stdint.h>

#define NB 16
#define D_NEED 29      // frames d = 31..59
#define D_OFF 31
#define T_NEED 15      // t = 45..59

#define BANDS 11600         // NB * 725 bands of 10 input rows
#define GRID_A 888          // 6 blocks per SM
#define STAGES 2
#define BAND_FLOATS 2500    // 10 rows * 250 cols
#define BAND_BYTES 10000    // multiple of 16

// scratch (no allocations allowed)
__device__ float g_s1[NB * D_NEED * 2500];     // spatial-conv output, [b][29][50x50]

__device__ __forceinline__ unsigned su32(const void* p) {
    return (unsigned)__cvta_generic_to_shared(p);
}

__device__ __forceinline__ void mbar_wait(unsigned mbar, unsigned phase) {
    unsigned done = 0;
    do {
        asm volatile(
            "{\n\t.reg .pred p;\n\t"
            "mbarrier.try_wait.parity.shared.b64 p, [%1], %2, 10000000;\n\t"
            "selp.b32 %0, 1, 0, p;\n\t}"
            : "=r"(done) : "r"(mbar), "r"(phase) : "memory");
    } while (!done);
}

// ---------------------------------------------------------------------------
// Kernel A: 5x5 stride-5 spatial conv on frames 31..59.
// 888 blocks (6/SM), 128 threads, 2-stage x 10 KB TMA pipeline (20 KB smem).
// Band id -> b = id/725, dIdx = (id%725)/25, g = id%25 : 2 output rows.
// Many independent blocks per SM -> statistical multiplexing of TMA waits.
// ---------------------------------------------------------------------------
__global__ void __launch_bounds__(128) kA(const float* __restrict__ x,
                                          const float* __restrict__ sw)
{
    extern __shared__ float dbuf[];                 // STAGES * 2500 floats
    __shared__ unsigned long long mbar[STAGES];
    __shared__ float w[25];
    const int tid = threadIdx.x;

    unsigned mb[STAGES], bb[STAGES];
    #pragma unroll
    for (int s = 0; s < STAGES; s++) {
        mb[s] = su32(&mbar[s]);
        bb[s] = su32(dbuf + s * BAND_FLOATS);
    }

    if (tid == 0) {
        #pragma unroll
        for (int s = 0; s < STAGES; s++)
            asm volatile("mbarrier.init.shared.b64 [%0], 1;" :: "r"(mb[s]) : "memory");
        asm volatile("fence.proxy.async.shared::cta;" ::: "memory");
    }
    if (tid < 25) w[tid] = sw[tid];
    __syncthreads();

    const int nMine = (BANDS - 1 - (int)blockIdx.x) / GRID_A + 1;

    auto issueTMA = [&](int j) {
        const int id  = blockIdx.x + j * GRID_A;
        const int b   = id / 725;
        const int rem = id % 725;
        const float* src = x + (size_t)(b * 60 + D_OFF) * 62500u
                             + (size_t)rem * BAND_FLOATS;
        const int s = j & (STAGES - 1);
        asm volatile("mbarrier.arrive.expect_tx.shared.b64 _, [%0], %1;"
                     :: "r"(mb[s]), "n"(BAND_BYTES) : "memory");
        asm volatile("cp.async.bulk.shared::cta.global.mbarrier::complete_tx::bytes "
                     "[%0], [%1], %2, [%3];"
                     :: "r"(bb[s]), "l"(src), "n"(BAND_BYTES), "r"(mb[s]) : "memory");
    };

    if (tid == 0 && nMine > 0) issueTMA(0);

    for (int j = 0; j < nMine; j++) {
        // issue band j+1: its buffer was freed by iteration j-1's sync
        if (tid == 0 && j + 1 < nMine) issueTMA(j + 1);

        const int s = j & (STAGES - 1);
        mbar_wait(mb[s], (j >> 1) & 1);

        const int id = blockIdx.x + j * GRID_A;
        if (tid < 100) {
            const float* p = dbuf + s * BAND_FLOATS
                           + (tid / 50) * 1250 + (tid % 50) * 5;
            float acc = 0.f;
            #pragma unroll
            for (int i = 0; i < 5; i++)
                #pragma unroll
                for (int jj = 0; jj < 5; jj++)
                    acc = fmaf(w[i * 5 + jj], p[i * 250 + jj], acc);
            // global output row R = id%725 * 2 + tid/50  (within batch),
            // g_s1 layout [b][R][50] with R in [0,1450)
            g_s1[id * 100 + tid] = acc;
        }
        __syncthreads();                 // all reads of buffer s done
    }
}

// ---------------------------------------------------------------------------
// Kernel BC (fused): temporal 15-tap conv + ReLU -> last 5x5/stride-5 conv
// -> ama/gang cone at t=59 -> out[b].  grid = 16 (one block per batch),
// block = 1024, dyn smem = first[15*2500] + flat[15*100] floats.
// ---------------------------------------------------------------------------
__global__ void __launch_bounds__(1024) kBC(const float* __restrict__ tw_g,
                                            const float* __restrict__ lw_g,
                                            const float* __restrict__ acw,
                                            const float* __restrict__ akw,
                                            const float* __restrict__ akb,
                                            const float* __restrict__ alw,
                                            const float* __restrict__ gcw,
                                            const float* __restrict__ gkw,
                                            const float* __restrict__ gkb,
                                            const float* __restrict__ gcolw,
                                            float* __restrict__ out)
{
    extern __shared__ float smem[];
    float* first = smem;                  // [15][2500]
    float* flat  = smem + T_NEED * 2500;  // [15][100]
    __shared__ float tw[15];
    __shared__ float lw[25];
    __shared__ float red[49];
    const int b   = blockIdx.x;
    const int tid = threadIdx.x;

    if (tid < 15) tw[tid] = tw_g[tid];
    if (tid >= 32 && tid < 57) lw[tid - 32] = lw_g[tid - 32];
    __syncthreads();

    // Phase 1: temporal conv + relu, g_s1 read exactly once (coalesced)
    for (int col = tid; col < 2500; col += 1024) {
        const float* src = g_s1 + (size_t)b * (D_NEED * 2500) + col;
        float v[D_NEED];
        #pragma unroll
        for (int d = 0; d < D_NEED; d++) v[d] = src[d * 2500];
        #pragma unroll
        for (int t = 0; t < T_NEED; t++) {
            float acc = 0.f;
            #pragma unroll
            for (int k = 0; k < 15; k++)
                acc = fmaf(tw[k], v[t + k], acc);
            first[t * 2500 + col] = fmaxf(acc, 0.f);
        }
    }
    __syncthreads();

    // Phase 2: last conv (5x5 stride 5) -> flat[t][100]
    for (int i = tid; i < T_NEED * 100; i += 1024) {
        const int t = i / 100, m = i % 100;
        const int h = m / 10, c = m % 10;
        const float* p = first + t * 2500 + h * 5 * 50 + c * 5;
        float acc = 0.f;
        #pragma unroll
        for (int ii = 0; ii < 5; ii++)
            #pragma unroll
            for (int jj = 0; jj < 5; jj++)
                acc = fmaf(lw[ii * 5 + jj], p[ii * 50 + jj], acc);
        flat[i] = acc;
    }
    __syncthreads();

    // Phase 3: ama/gang cone at t=59
    if (tid < 49) {
        const float ac = acw[0], al = alw[0], gc = gcw[0];
        const int ja = 2 * tid;
        const int jg = (2 * tid + 25) % 100;
        float a = akb[0];
        float g = gkb[0];
        #pragma unroll
        for (int k = 0; k < 15; k++) {
            a = fmaf(akw[k], ac * flat[k * 100 + ja], a);
            g = fmaf(gkw[k], gc * flat[k * 100 + jg], g);
        }
        const float amo = al / (1.f + expf(-a));
        const float val = 1.f / (1.f + expf(-(g - fabsf(amo))));
        red[tid] = gcolw[tid] * val;
    }
    __syncthreads();

    if (tid == 0) {
        float s = 0.f;
        #pragma unroll
        for (int j = 0; j < 49; j++) s += red[j];
        out[b] = s;
    }
}

// ---------------------------------------------------------------------------
extern "C" void kernel_launch(void* const* d_in, const int* in_sizes, int n_in,
                              void* d_out, int out_size)
{
    const float* x          = (const float*)d_in[0];
    const float* space_w    = (const float*)d_in[1];
    const float* temporal_w = (const float*)d_in[2];
    const float* last_w     = (const float*)d_in[3];
    const float* ama_create = (const float*)d_in[4];
    const float* ama_kern   = (const float*)d_in[5];
    const float* ama_kern_b = (const float*)d_in[6];
    const float* ama_alpha  = (const float*)d_in[7];
    const float* gang_create= (const float*)d_in[8];
    const float* gang_kern  = (const float*)d_in[9];
    const float* gang_kern_b= (const float*)d_in[10];
    const float* gang_col   = (const float*)d_in[11];
    float* out = (float*)d_out;

    const int dynA = STAGES * BAND_BYTES;                 // 20000 bytes
    cudaFuncSetAttribute(kA, cudaFuncAttributeMaxDynamicSharedMemorySize, dynA);
    const int dynBC = (T_NEED * 2500 + T_NEED * 100) * 4; // 156000 bytes
    cudaFuncSetAttribute(kBC, cudaFuncAttributeMaxDynamicSharedMemorySize, dynBC);

    kA<<<GRID_A, 128, dynA>>>(x, space_w);

    kBC<<<NB, 1024, dynBC>>>(temporal_w, last_w,
                             ama_create, ama_kern, ama_kern_b, ama_alpha,
                             gang_create, gang_kern, gang_kern_b, gang_col, out);
}

// round 8
// speedup vs baseline: 1.0650x; 1.0650x over previous
#include <cuda_runtime.h>
#include <math.h>
#include <stdint.h>

#define NB 16
#define D_NEED 29      // frames d = 31..59
#define D_OFF 31
#define T_NEED 15      // t = 45..59

#define BANDS 11600         // NB * 725 bands of 10 input rows
#define GRID_A 1184         // 8 blocks per SM
#define STAGES 2
#define BAND_FLOATS 2500    // 10 rows * 250 cols
#define BAND_BYTES 10000    // multiple of 16

// scratch (no allocations allowed)
__device__ float g_s1[NB * D_NEED * 2500];     // spatial-conv output, [b][29][50x50]
__device__ float g_flat[NB * T_NEED * 100];    // last-conv output, 100 per (b,t)

__device__ __forceinline__ unsigned su32(const void* p) {
    return (unsigned)__cvta_generic_to_shared(p);
}

__device__ __forceinline__ void mbar_wait(unsigned mbar, unsigned phase) {
    unsigned done = 0;
    do {
        asm volatile(
            "{\n\t.reg .pred p;\n\t"
            "mbarrier.try_wait.parity.shared.b64 p, [%1], %2, 10000000;\n\t"
            "selp.b32 %0, 1, 0, p;\n\t}"
            : "=r"(done) : "r"(mbar), "r"(phase) : "memory");
    } while (!done);
}

// ---------------------------------------------------------------------------
// Kernel A: 5x5 stride-5 spatial conv on frames 31..59.
// 1184 blocks (8/SM), 128 threads, 2-stage x 10 KB TMA pipeline (20 KB smem).
// Band id -> b = id/725, rem = id%725 : rows rem*10..rem*10+9 of frame block.
// Many independent blocks per SM -> statistical multiplexing of TMA waits.
// ---------------------------------------------------------------------------
__global__ void __launch_bounds__(128) kA(const float* __restrict__ x,
                                          const float* __restrict__ sw)
{
    extern __shared__ float dbuf[];                 // STAGES * 2500 floats
    __shared__ unsigned long long mbar[STAGES];
    __shared__ float w[25];
    const int tid = threadIdx.x;

    unsigned mb[STAGES], bb[STAGES];
    #pragma unroll
    for (int s = 0; s < STAGES; s++) {
        mb[s] = su32(&mbar[s]);
        bb[s] = su32(dbuf + s * BAND_FLOATS);
    }

    if (tid == 0) {
        #pragma unroll
        for (int s = 0; s < STAGES; s++)
            asm volatile("mbarrier.init.shared.b64 [%0], 1;" :: "r"(mb[s]) : "memory");
        asm volatile("fence.proxy.async.shared::cta;" ::: "memory");
    }
    if (tid < 25) w[tid] = sw[tid];
    __syncthreads();

    const int nMine = (BANDS - 1 - (int)blockIdx.x) / GRID_A + 1;

    auto issueTMA = [&](int j) {
        const int id  = blockIdx.x + j * GRID_A;
        const int b   = id / 725;
        const int rem = id % 725;
        const float* src = x + (size_t)(b * 60 + D_OFF) * 62500u
                             + (size_t)rem * BAND_FLOATS;
        const int s = j & (STAGES - 1);
        asm volatile("mbarrier.arrive.expect_tx.shared.b64 _, [%0], %1;"
                     :: "r"(mb[s]), "n"(BAND_BYTES) : "memory");
        asm volatile("cp.async.bulk.shared::cta.global.mbarrier::complete_tx::bytes "
                     "[%0], [%1], %2, [%3];"
                     :: "r"(bb[s]), "l"(src), "n"(BAND_BYTES), "r"(mb[s]) : "memory");
    };

    if (tid == 0 && nMine > 0) issueTMA(0);

    for (int j = 0; j < nMine; j++) {
        // issue band j+1: its buffer was freed by iteration j-1's sync
        if (tid == 0 && j + 1 < nMine) issueTMA(j + 1);

        const int s = j & (STAGES - 1);
        mbar_wait(mb[s], (j >> 1) & 1);

        const int id = blockIdx.x + j * GRID_A;
        if (tid < 100) {
            const float* p = dbuf + s * BAND_FLOATS
                           + (tid / 50) * 1250 + (tid % 50) * 5;
            float acc = 0.f;
            #pragma unroll
            for (int i = 0; i < 5; i++)
                #pragma unroll
                for (int jj = 0; jj < 5; jj++)
                    acc = fmaf(w[i * 5 + jj], p[i * 250 + jj], acc);
            g_s1[id * 100 + tid] = acc;
        }
        __syncthreads();                 // all reads of buffer s done
    }
}

// ---------------------------------------------------------------------------
// Kernel B: temporal 15-tap conv + ReLU + 5x5/stride-5 last conv.
// grid = (10 row-groups, 16 batches), block = 256. Reads g_s1 exactly once.
// ---------------------------------------------------------------------------
__global__ void __launch_bounds__(256) kB(const float* __restrict__ tw_g,
                                          const float* __restrict__ lw_g)
{
    __shared__ float sfirst[T_NEED * 250];   // [t][5 rows x 50 cols]
    __shared__ float tw[15];
    __shared__ float lw[25];
    const int grp = blockIdx.x;   // output row h = grp, pixels grp*250..+249
    const int b   = blockIdx.y;
    const int tid = threadIdx.x;

    if (tid < 15) tw[tid] = tw_g[tid];
    if (tid >= 32 && tid < 57) lw[tid - 32] = lw_g[tid - 32];
    __syncthreads();

    if (tid < 250) {
        const float* src = g_s1 + (size_t)b * (D_NEED * 2500) + grp * 250 + tid;
        float v[D_NEED];
        #pragma unroll
        for (int d = 0; d < D_NEED; d++) v[d] = src[d * 2500];
        #pragma unroll
        for (int t = 0; t < T_NEED; t++) {
            float acc = 0.f;
            #pragma unroll
            for (int k = 0; k < 15; k++)
                acc = fmaf(tw[k], v[t + k], acc);
            sfirst[t * 250 + tid] = fmaxf(acc, 0.f);
        }
    }
    __syncthreads();

    if (tid < 150) {
        const int t = tid / 10, c = tid % 10;
        const float* p = sfirst + t * 250 + c * 5;
        float acc = 0.f;
        #pragma unroll
        for (int i = 0; i < 5; i++)
            #pragma unroll
            for (int j = 0; j < 5; j++)
                acc = fmaf(lw[i * 5 + j], p[i * 50 + j], acc);
        g_flat[(b * T_NEED + t) * 100 + grp * 10 + c] = acc;
    }
}

// ---------------------------------------------------------------------------
// Kernel C: ama/gang cone at t=59 + 49-tap dot product. grid = 16, block = 64.
// ---------------------------------------------------------------------------
__global__ void __launch_bounds__(64) kC(const float* __restrict__ acw,
                                         const float* __restrict__ akw,
                                         const float* __restrict__ akb,
                                         const float* __restrict__ alw,
                                         const float* __restrict__ gcw,
                                         const float* __restrict__ gkw,
                                         const float* __restrict__ gkb,
                                         const float* __restrict__ gcolw,
                                         float* __restrict__ out)
{
    __shared__ float fl[T_NEED * 100];
    __shared__ float red[49];
    const int b   = blockIdx.x;
    const int tid = threadIdx.x;

    for (int i = tid; i < T_NEED * 100; i += 64)
        fl[i] = g_flat[b * (T_NEED * 100) + i];
    __syncthreads();

    if (tid < 49) {
        const float ac = acw[0], al = alw[0], gc = gcw[0];
        const int ja = 2 * tid;
        const int jg = (2 * tid + 25) % 100;
        float a = akb[0];
        float g = gkb[0];
        #pragma unroll
        for (int k = 0; k < 15; k++) {
            a = fmaf(akw[k], ac * fl[k * 100 + ja], a);
            g = fmaf(gkw[k], gc * fl[k * 100 + jg], g);
        }
        const float amo = al / (1.f + expf(-a));
        const float val = 1.f / (1.f + expf(-(g - fabsf(amo))));
        red[tid] = gcolw[tid] * val;
    }
    __syncthreads();

    if (tid == 0) {
        float s = 0.f;
        #pragma unroll
        for (int j = 0; j < 49; j++) s += red[j];
        out[b] = s;
    }
}

// ---------------------------------------------------------------------------
extern "C" void kernel_launch(void* const* d_in, const int* in_sizes, int n_in,
                              void* d_out, int out_size)
{
    const float* x          = (const float*)d_in[0];
    const float* space_w    = (const float*)d_in[1];
    const float* temporal_w = (const float*)d_in[2];
    const float* last_w     = (const float*)d_in[3];
    const float* ama_create = (const float*)d_in[4];
    const float* ama_kern   = (const float*)d_in[5];
    const float* ama_kern_b = (const float*)d_in[6];
    const float* ama_alpha  = (const float*)d_in[7];
    const float* gang_create= (const float*)d_in[8];
    const float* gang_kern  = (const float*)d_in[9];
    const float* gang_kern_b= (const float*)d_in[10];
    const float* gang_col   = (const float*)d_in[11];
    float* out = (float*)d_out;

    const int dynA = STAGES * BAND_BYTES;   // 20000 bytes
    cudaFuncSetAttribute(kA, cudaFuncAttributeMaxDynamicSharedMemorySize, dynA);

    kA<<<GRID_A, 128, dynA>>>(x, space_w);

    dim3 gB(10, NB);
    kB<<<gB, 256>>>(temporal_w, last_w);

    kC<<<NB, 64>>>(ama_create, ama_kern, ama_kern_b, ama_alpha,
                   gang_create, gang_kern, gang_kern_b, gang_col, out);
}

// round 9
// speedup vs baseline: 1.0661x; 1.0010x over previous
#include <cuda_runtime.h>
#include <math.h>
#include <stdint.h>

#define NB 16
#define D_NEED 29      // frames d = 31..59
#define D_OFF 31
#define T_NEED 15      // t = 45..59

#define N_OUT (NB * D_NEED * 2500)   // 1,160,000 spatial-conv outputs

// scratch (no allocations allowed)
__device__ float g_s1[NB * D_NEED * 2500];     // spatial-conv output, [b][29][50x50]
__device__ float g_flat[NB * T_NEED * 100];    // last-conv output, 100 per (b,t)

// ---------------------------------------------------------------------------
// Kernel A: 5x5 stride-5 spatial conv on frames 31..59 — DIRECT, no smem.
// 1 thread = 1 output pixel. Warp reads 160 contiguous bytes per row-iter
// (fully coalesced); every input byte fetched exactly once; 25 independent
// loads per thread (MLP=25); zero barriers -> uniform DRAM demand.
// ---------------------------------------------------------------------------
__global__ void __launch_bounds__(256) kA(const float* __restrict__ x,
                                          const float* __restrict__ sw)
{
    const int id = blockIdx.x * 256 + threadIdx.x;
    if (id >= N_OUT) return;

    const int ocol = id % 50;
    const int orow = (id / 50) % 50;
    const int f    = id / 2500;             // 0..463 = b*29 + dIdx
    const int b    = f / D_NEED;
    const int dIdx = f % D_NEED;

    const float* p = x + (size_t)(b * 60 + D_OFF + dIdx) * 62500u
                       + orow * 1250 + ocol * 5;

    // load 25 inputs (independent), 5 partial accumulators for FMA overlap
    float v[25];
    #pragma unroll
    for (int i = 0; i < 5; i++)
        #pragma unroll
        for (int j = 0; j < 5; j++)
            v[i * 5 + j] = __ldg(p + i * 250 + j);

    float a0 = 0.f, a1 = 0.f, a2 = 0.f, a3 = 0.f, a4 = 0.f;
    #pragma unroll
    for (int j = 0; j < 5; j++) {
        a0 = fmaf(sw[0 * 5 + j],  v[0 * 5 + j], a0);
        a1 = fmaf(sw[1 * 5 + j],  v[1 * 5 + j], a1);
        a2 = fmaf(sw[2 * 5 + j],  v[2 * 5 + j], a2);
        a3 = fmaf(sw[3 * 5 + j],  v[3 * 5 + j], a3);
        a4 = fmaf(sw[4 * 5 + j],  v[4 * 5 + j], a4);
    }
    g_s1[id] = ((a0 + a1) + (a2 + a3)) + a4;
}

// ---------------------------------------------------------------------------
// Kernel B: temporal 15-tap conv + ReLU + 5x5/stride-5 last conv.
// grid = (10 row-groups, 16 batches), block = 256. Reads g_s1 exactly once.
// ---------------------------------------------------------------------------
__global__ void __launch_bounds__(256) kB(const float* __restrict__ tw_g,
                                          const float* __restrict__ lw_g)
{
    __shared__ float sfirst[T_NEED * 250];   // [t][5 rows x 50 cols]
    __shared__ float tw[15];
    __shared__ float lw[25];
    const int grp = blockIdx.x;   // output row h = grp, pixels grp*250..+249
    const int b   = blockIdx.y;
    const int tid = threadIdx.x;

    if (tid < 15) tw[tid] = tw_g[tid];
    if (tid >= 32 && tid < 57) lw[tid - 32] = lw_g[tid - 32];
    __syncthreads();

    if (tid < 250) {
        const float* src = g_s1 + (size_t)b * (D_NEED * 2500) + grp * 250 + tid;
        float v[D_NEED];
        #pragma unroll
        for (int d = 0; d < D_NEED; d++) v[d] = src[d * 2500];
        #pragma unroll
        for (int t = 0; t < T_NEED; t++) {
            float acc = 0.f;
            #pragma unroll
            for (int k = 0; k < 15; k++)
                acc = fmaf(tw[k], v[t + k], acc);
            sfirst[t * 250 + tid] = fmaxf(acc, 0.f);
        }
    }
    __syncthreads();

    if (tid < 150) {
        const int t = tid / 10, c = tid % 10;
        const float* p = sfirst + t * 250 + c * 5;
        float acc = 0.f;
        #pragma unroll
        for (int i = 0; i < 5; i++)
            #pragma unroll
            for (int j = 0; j < 5; j++)
                acc = fmaf(lw[i * 5 + j], p[i * 50 + j], acc);
        g_flat[(b * T_NEED + t) * 100 + grp * 10 + c] = acc;
    }
}

// ---------------------------------------------------------------------------
// Kernel C: ama/gang cone at t=59 + 49-tap dot product. grid = 16, block = 64.
// ---------------------------------------------------------------------------
__global__ void __launch_bounds__(64) kC(const float* __restrict__ acw,
                                         const float* __restrict__ akw,
                                         const float* __restrict__ akb,
                                         const float* __restrict__ alw,
                                         const float* __restrict__ gcw,
                                         const float* __restrict__ gkw,
                                         const float* __restrict__ gkb,
                                         const float* __restrict__ gcolw,
                                         float* __restrict__ out)
{
    __shared__ float fl[T_NEED * 100];
    __shared__ float red[49];
    const int b   = blockIdx.x;
    const int tid = threadIdx.x;

    for (int i = tid; i < T_NEED * 100; i += 64)
        fl[i] = g_flat[b * (T_NEED * 100) + i];
    __syncthreads();

    if (tid < 49) {
        const float ac = acw[0], al = alw[0], gc = gcw[0];
        const int ja = 2 * tid;
        const int jg = (2 * tid + 25) % 100;
        float a = akb[0];
        float g = gkb[0];
        #pragma unroll
        for (int k = 0; k < 15; k++) {
            a = fmaf(akw[k], ac * fl[k * 100 + ja], a);
            g = fmaf(gkw[k], gc * fl[k * 100 + jg], g);
        }
        const float amo = al / (1.f + expf(-a));
        const float val = 1.f / (1.f + expf(-(g - fabsf(amo))));
        red[tid] = gcolw[tid] * val;
    }
    __syncthreads();

    if (tid == 0) {
        float s = 0.f;
        #pragma unroll
        for (int j = 0; j < 49; j++) s += red[j];
        out[b] = s;
    }
}

// ---------------------------------------------------------------------------
extern "C" void kernel_launch(void* const* d_in, const int* in_sizes, int n_in,
                              void* d_out, int out_size)
{
    const float* x          = (const float*)d_in[0];
    const float* space_w    = (const float*)d_in[1];
    const float* temporal_w = (const float*)d_in[2];
    const float* last_w     = (const float*)d_in[3];
    const float* ama_create = (const float*)d_in[4];
    const float* ama_kern   = (const float*)d_in[5];
    const float* ama_kern_b = (const float*)d_in[6];
    const float* ama_alpha  = (const float*)d_in[7];
    const float* gang_create= (const float*)d_in[8];
    const float* gang_kern  = (const float*)d_in[9];
    const float* gang_kern_b= (const float*)d_in[10];
    const float* gang_col   = (const float*)d_in[11];
    float* out = (float*)d_out;

    kA<<<(N_OUT + 255) / 256, 256>>>(x, space_w);

    dim3 gB(10, NB);
    kB<<<gB, 256>>>(temporal_w, last_w);

    kC<<<NB, 64>>>(ama_create, ama_kern, ama_kern_b, ama_alpha,
                   gang_create, gang_kern, gang_kern_b, gang_col, out);
}